// round 4
// baseline (speedup 1.0000x reference)
#include <cuda_runtime.h>

#define CIN  128
#define CTOT 128   // [mu(64) | logstd(64)]
#define COUT 64
#define NMAX 100000
#define MAX_LOGSTD 10.0f

// Scratch (device globals: no allocations allowed)
__device__ float g_deg[NMAX];
__device__ float g_feat[(size_t)NMAX * CTOT];  // g = (x @ [Wmu|Wls]) * dinv[row]
__device__ float g_acc [(size_t)NMAX * CTOT];  // scatter accumulator (init = g, self-loop)
__device__ int   g_is64;                       // 1 if edge_index really is int64

// ---------------------------------------------------------------------------
// 0a) reset dtype flag (graph replays must be deterministic)
__global__ void reset_flag_kernel() {
    if (threadIdx.x == 0 && blockIdx.x == 0) g_is64 = 1;
}

// 0b) dtype detect: read first E slots AS int64 (= first 8E bytes; buffer is
//     8E bytes if int64, 8E bytes total (2E*4) if int32 -> never OOB).
//     If any value falls outside [0,N), the data cannot be int64 node indices.
__global__ void detect_kernel(const long long* __restrict__ ei, long long E, int N) {
    long long i = (long long)blockIdx.x * blockDim.x + threadIdx.x;
    if (i < E) {
        long long v = ei[i];
        if (v < 0 || v >= N) g_is64 = 0;   // racy write of same value: fine
    }
}

__device__ __forceinline__ int load_idx(const void* ei, long long slot) {
    return g_is64 ? (int)((const long long*)ei)[slot]
                  : ((const int*)ei)[slot];
}

// 1) degree init (self-loop contributes 1)
__global__ void init_deg_kernel(int N) {
    int i = blockIdx.x * blockDim.x + threadIdx.x;
    if (i < N) g_deg[i] = 1.0f;
}

// 2) degree count over dst
__global__ void deg_kernel(const void* __restrict__ ei, long long E, int N) {
    long long i = (long long)blockIdx.x * blockDim.x + threadIdx.x;
    if (i < E) {
        int dst = load_idx(ei, E + i);
        if ((unsigned)dst < (unsigned)N) atomicAdd(&g_deg[dst], 1.0f);
    }
}

// 3) GEMM: g_feat[row] = (x[row] @ [Wmu|Wls]) * rsqrt(deg[row]); g_acc = g_feat
//    BM=64, BN=128(full), BK=32. 256 threads, each computes 4 rows x 8 cols.
__global__ __launch_bounds__(256) void gemm_kernel(
    const float* __restrict__ x,
    const float* __restrict__ Wmu,
    const float* __restrict__ Wls,
    int N)
{
    __shared__ float w_s[32 * 128];   // [k_local][c]
    __shared__ float x_s[32 * 68];    // [k_local][row] padded 64->68

    const int tid  = threadIdx.x;
    const int row0 = blockIdx.x * 64;
    const int ty   = tid >> 4;        // 0..15 -> row group
    const int tx   = tid & 15;        // 0..15 -> col group
    const int r0   = ty * 4;

    float acc[4][8];
    #pragma unroll
    for (int i = 0; i < 4; i++)
        #pragma unroll
        for (int j = 0; j < 8; j++) acc[i][j] = 0.0f;

    for (int kt = 0; kt < 4; kt++) {
        // load W tile: 32x128 floats, 16 per thread (coalesced over c)
        #pragma unroll
        for (int j = 0; j < 16; j++) {
            int idx = tid + j * 256;
            int kl = idx >> 7, c = idx & 127;
            int k = kt * 32 + kl;
            w_s[idx] = (c < 64) ? Wmu[k * 64 + c] : Wls[k * 64 + (c - 64)];
        }
        // load x tile transposed: [kl][row], 8 per thread (coalesced global read over k)
        #pragma unroll
        for (int j = 0; j < 8; j++) {
            int idx = tid + j * 256;
            int r = idx >> 5, kl = idx & 31;
            int row = row0 + r;
            float v = (row < N) ? x[(size_t)row * CIN + kt * 32 + kl] : 0.0f;
            x_s[kl * 68 + r] = v;
        }
        __syncthreads();

        #pragma unroll
        for (int kl = 0; kl < 32; kl++) {
            float4 xa = *(const float4*)&x_s[kl * 68 + r0];
            float4 wa = *(const float4*)&w_s[kl * 128 + tx * 4];
            float4 wb = *(const float4*)&w_s[kl * 128 + 64 + tx * 4];
            float xr[4] = {xa.x, xa.y, xa.z, xa.w};
            float wc[8] = {wa.x, wa.y, wa.z, wa.w, wb.x, wb.y, wb.z, wb.w};
            #pragma unroll
            for (int i = 0; i < 4; i++)
                #pragma unroll
                for (int j = 0; j < 8; j++)
                    acc[i][j] += xr[i] * wc[j];
        }
        __syncthreads();
    }

    // epilogue: scale by dinv, write g_feat and g_acc (self-loop init)
    #pragma unroll
    for (int i = 0; i < 4; i++) {
        int row = row0 + r0 + i;
        if (row >= N) continue;
        float dinv = rsqrtf(g_deg[row]);
        float4 va = make_float4(acc[i][0] * dinv, acc[i][1] * dinv,
                                acc[i][2] * dinv, acc[i][3] * dinv);
        float4 vb = make_float4(acc[i][4] * dinv, acc[i][5] * dinv,
                                acc[i][6] * dinv, acc[i][7] * dinv);
        size_t base = (size_t)row * CTOT;
        *(float4*)&g_feat[base + tx * 4]      = va;
        *(float4*)&g_feat[base + 64 + tx * 4] = vb;
        *(float4*)&g_acc [base + tx * 4]      = va;
        *(float4*)&g_acc [base + 64 + tx * 4] = vb;
    }
}

// 4) edge scatter: one warp per edge. lane loads float4 of g_feat[src],
//    then 4 scalar reductions (REDG.ADD.F32) into g_acc[dst].
__global__ __launch_bounds__(256) void scatter_kernel(const void* __restrict__ ei,
                                                      long long E, int N)
{
    long long w = (long long)blockIdx.x * (blockDim.x >> 5) + (threadIdx.x >> 5);
    if (w >= E) return;
    int lane = threadIdx.x & 31;
    int src = load_idx(ei, w);
    int dst = load_idx(ei, E + w);
    if ((unsigned)src >= (unsigned)N || (unsigned)dst >= (unsigned)N) return;
    const float4* vs = (const float4*)(g_feat + (size_t)src * CTOT);
    float4 v = vs[lane];
    float* p = g_acc + (size_t)dst * CTOT + lane * 4;
    atomicAdd(p + 0, v.x);
    atomicAdd(p + 1, v.y);
    atomicAdd(p + 2, v.z);
    atomicAdd(p + 3, v.w);
}

// 5) finalize: mu = acc_mu*dinv + b_mu ; ls = min(acc_ls*dinv + b_ls, 10)
//    z = mu + eps * exp(ls)
__global__ void final_kernel(const float* __restrict__ b_mu,
                             const float* __restrict__ b_ls,
                             const float* __restrict__ eps,
                             float* __restrict__ out,
                             int N)
{
    int id = blockIdx.x * blockDim.x + threadIdx.x;
    if (id >= N * COUT) return;
    int node = id >> 6;
    int c    = id & 63;
    float dinv = rsqrtf(g_deg[node]);
    size_t base = (size_t)node * CTOT;
    float mu = g_acc[base + c]      * dinv + b_mu[c];
    float ls = fminf(g_acc[base + 64 + c] * dinv + b_ls[c], MAX_LOGSTD);
    out[id] = mu + eps[id] * expf(ls);
}

extern "C" void kernel_launch(void* const* d_in, const int* in_sizes, int n_in,
                              void* d_out, int out_size)
{
    const float* x   = (const float*)d_in[0];
    const void*  ei  = d_in[1];                 // int32 or int64, detected on device
    const float* Wmu = (const float*)d_in[2];
    const float* bmu = (const float*)d_in[3];
    const float* Wls = (const float*)d_in[4];
    const float* bls = (const float*)d_in[5];
    const float* eps = (const float*)d_in[6];
    float*       out = (float*)d_out;

    int N = in_sizes[0] / CIN;          // 100000
    long long E = in_sizes[1] / 2;      // 1600000

    reset_flag_kernel<<<1, 32>>>();
    detect_kernel<<<(int)((E + 255) / 256), 256>>>((const long long*)ei, E, N);
    init_deg_kernel<<<(N + 255) / 256, 256>>>(N);
    deg_kernel<<<(int)((E + 255) / 256), 256>>>(ei, E, N);
    gemm_kernel<<<(N + 63) / 64, 256>>>(x, Wmu, Wls, N);
    scatter_kernel<<<(int)((E + 7) / 8), 256>>>(ei, E, N);
    final_kernel<<<(N * COUT + 255) / 256, 256>>>(bmu, bls, eps, out, N);
}

// round 5
// speedup vs baseline: 1.4885x; 1.4885x over previous
#include <cuda_runtime.h>

#define CIN  128
#define CTOT 128   // [mu(64) | logstd(64)]
#define COUT 64
#define NMAX 100000
#define EMAX 2000000
#define MAX_LOGSTD 10.0f

// Scratch (device globals: no allocations allowed)
__device__ float g_feat[(size_t)NMAX * CTOT];  // g = (x @ [Wmu|Wls]) * dinv[row]
__device__ int   g_cnt [NMAX];                 // in-degree (without self-loop)
__device__ int   g_ptr [NMAX + 1];             // CSR row pointers (exclusive scan)
__device__ int   g_cur [NMAX];                 // fill cursors (copy of g_ptr)
__device__ int   g_srcs[EMAX];                 // CSR column (src) indices
__device__ int   g_is64;                       // 1 if edge_index really is int64

// ---------------------------------------------------------------------------
// 0) zero counts + reset dtype flag (graph replays must be deterministic)
__global__ void zero_kernel(int N) {
    int i = blockIdx.x * blockDim.x + threadIdx.x;
    if (i < N) g_cnt[i] = 0;
    if (i == 0) g_is64 = 1;
}

// 0b) dtype detect: read first E slots AS int64 (first 8E bytes; buffer is
//     >= 8E bytes under either dtype -> never OOB). Any value outside [0,N)
//     means the data cannot be int64 node indices.
__global__ void detect_kernel(const long long* __restrict__ ei, long long E, int N) {
    long long i = (long long)blockIdx.x * blockDim.x + threadIdx.x;
    if (i < E) {
        long long v = ei[i];
        if (v < 0 || v >= N) g_is64 = 0;   // racy same-value write: fine
    }
}

__device__ __forceinline__ int load_idx(const void* ei, long long slot) {
    return g_is64 ? (int)((const long long*)ei)[slot]
                  : ((const int*)ei)[slot];
}

// 1) in-degree count over dst
__global__ void count_kernel(const void* __restrict__ ei, long long E, int N) {
    long long i = (long long)blockIdx.x * blockDim.x + threadIdx.x;
    if (i < E) {
        int dst = load_idx(ei, E + i);
        if ((unsigned)dst < (unsigned)N) atomicAdd(&g_cnt[dst], 1);
    }
}

// 2) exclusive scan of g_cnt -> g_ptr, g_cur.  Single block, 1024 threads,
//    98 chunk iterations over 100K elements.
__global__ __launch_bounds__(1024) void scan_kernel(int N) {
    __shared__ int warp_sums[32];
    __shared__ int s_carry;
    int tid  = threadIdx.x;
    int lane = tid & 31;
    int wid  = tid >> 5;
    if (tid == 0) s_carry = 0;
    __syncthreads();

    for (int base = 0; base < N; base += 1024) {
        int i = base + tid;
        int v = (i < N) ? g_cnt[i] : 0;
        int x = v;                       // inclusive scan within warp
        #pragma unroll
        for (int d = 1; d < 32; d <<= 1) {
            int y = __shfl_up_sync(0xFFFFFFFFu, x, d);
            if (lane >= d) x += y;
        }
        if (lane == 31) warp_sums[wid] = x;
        __syncthreads();
        if (wid == 0) {                  // scan the 32 warp totals
            int s = warp_sums[lane];
            #pragma unroll
            for (int d = 1; d < 32; d <<= 1) {
                int y = __shfl_up_sync(0xFFFFFFFFu, s, d);
                if (lane >= d) s += y;
            }
            warp_sums[lane] = s;
        }
        __syncthreads();
        int warp_off = (wid > 0) ? warp_sums[wid - 1] : 0;
        int excl = s_carry + warp_off + x - v;
        if (i < N) { g_ptr[i] = excl; g_cur[i] = excl; }
        __syncthreads();                 // all reads of s_carry done
        if (tid == 0) s_carry += warp_sums[31];
        __syncthreads();
    }
    if (tid == 0) g_ptr[N] = s_carry;
}

// 3) CSR fill: scatter src indices into dst-grouped order
__global__ void fill_kernel(const void* __restrict__ ei, long long E, int N) {
    long long i = (long long)blockIdx.x * blockDim.x + threadIdx.x;
    if (i < E) {
        int src = load_idx(ei, i);
        int dst = load_idx(ei, E + i);
        if ((unsigned)src < (unsigned)N && (unsigned)dst < (unsigned)N) {
            int pos = atomicAdd(&g_cur[dst], 1);
            if (pos < EMAX) g_srcs[pos] = src;
        }
    }
}

// 4) GEMM: g_feat[row] = (x[row] @ [Wmu|Wls]) * rsqrt(deg[row])
//    BM=64, BN=128(full), BK=32. 256 threads, each computes 4 rows x 8 cols.
__global__ __launch_bounds__(256) void gemm_kernel(
    const float* __restrict__ x,
    const float* __restrict__ Wmu,
    const float* __restrict__ Wls,
    int N)
{
    __shared__ float w_s[32 * 128];   // [k_local][c]
    __shared__ float x_s[32 * 68];    // [k_local][row] padded 64->68

    const int tid  = threadIdx.x;
    const int row0 = blockIdx.x * 64;
    const int ty   = tid >> 4;
    const int tx   = tid & 15;
    const int r0   = ty * 4;

    float acc[4][8];
    #pragma unroll
    for (int i = 0; i < 4; i++)
        #pragma unroll
        for (int j = 0; j < 8; j++) acc[i][j] = 0.0f;

    for (int kt = 0; kt < 4; kt++) {
        #pragma unroll
        for (int j = 0; j < 16; j++) {
            int idx = tid + j * 256;
            int kl = idx >> 7, c = idx & 127;
            int k = kt * 32 + kl;
            w_s[idx] = (c < 64) ? Wmu[k * 64 + c] : Wls[k * 64 + (c - 64)];
        }
        #pragma unroll
        for (int j = 0; j < 8; j++) {
            int idx = tid + j * 256;
            int r = idx >> 5, kl = idx & 31;
            int row = row0 + r;
            float v = (row < N) ? x[(size_t)row * CIN + kt * 32 + kl] : 0.0f;
            x_s[kl * 68 + r] = v;
        }
        __syncthreads();

        #pragma unroll
        for (int kl = 0; kl < 32; kl++) {
            float4 xa = *(const float4*)&x_s[kl * 68 + r0];
            float4 wa = *(const float4*)&w_s[kl * 128 + tx * 4];
            float4 wb = *(const float4*)&w_s[kl * 128 + 64 + tx * 4];
            float xr[4] = {xa.x, xa.y, xa.z, xa.w};
            float wc[8] = {wa.x, wa.y, wa.z, wa.w, wb.x, wb.y, wb.z, wb.w};
            #pragma unroll
            for (int i = 0; i < 4; i++)
                #pragma unroll
                for (int j = 0; j < 8; j++)
                    acc[i][j] += xr[i] * wc[j];
        }
        __syncthreads();
    }

    #pragma unroll
    for (int i = 0; i < 4; i++) {
        int row = row0 + r0 + i;
        if (row >= N) continue;
        float dinv = rsqrtf((float)g_cnt[row] + 1.0f);
        float4 va = make_float4(acc[i][0] * dinv, acc[i][1] * dinv,
                                acc[i][2] * dinv, acc[i][3] * dinv);
        float4 vb = make_float4(acc[i][4] * dinv, acc[i][5] * dinv,
                                acc[i][6] * dinv, acc[i][7] * dinv);
        size_t base = (size_t)row * CTOT;
        *(float4*)&g_feat[base + tx * 4]      = va;
        *(float4*)&g_feat[base + 64 + tx * 4] = vb;
    }
}

// 5) fused gather + finalize: one warp per node. Lane l owns float4 features
//    [4l, 4l+4) of the 128-wide fused row (lanes 0-15 = mu, 16-31 = logstd).
//    acc = g_feat[node] (self-loop) + sum over in-edges of g_feat[src].
//    z = (acc*dinv + b_mu) + eps * exp(min(acc*dinv + b_ls, 10)).
__global__ __launch_bounds__(256) void gather_kernel(
    const float* __restrict__ b_mu,
    const float* __restrict__ b_ls,
    const float* __restrict__ eps,
    float* __restrict__ out,
    int N)
{
    int node = blockIdx.x * 8 + (threadIdx.x >> 5);
    if (node >= N) return;
    int lane = threadIdx.x & 31;

    int beg = g_ptr[node];
    int end = g_ptr[node + 1];

    float4 a = ((const float4*)(g_feat + (size_t)node * CTOT))[lane];  // self-loop

    int e = beg;
    for (; e + 4 <= end; e += 4) {       // unroll 4 for MLP
        int s0 = g_srcs[e], s1 = g_srcs[e+1], s2 = g_srcs[e+2], s3 = g_srcs[e+3];
        float4 v0 = ((const float4*)(g_feat + (size_t)s0 * CTOT))[lane];
        float4 v1 = ((const float4*)(g_feat + (size_t)s1 * CTOT))[lane];
        float4 v2 = ((const float4*)(g_feat + (size_t)s2 * CTOT))[lane];
        float4 v3 = ((const float4*)(g_feat + (size_t)s3 * CTOT))[lane];
        a.x += (v0.x + v1.x) + (v2.x + v3.x);
        a.y += (v0.y + v1.y) + (v2.y + v3.y);
        a.z += (v0.z + v1.z) + (v2.z + v3.z);
        a.w += (v0.w + v1.w) + (v2.w + v3.w);
    }
    for (; e < end; e++) {
        int s = g_srcs[e];
        float4 v = ((const float4*)(g_feat + (size_t)s * CTOT))[lane];
        a.x += v.x; a.y += v.y; a.z += v.z; a.w += v.w;
    }

    float dinv = rsqrtf((float)g_cnt[node] + 1.0f);
    float4 b = (lane < 16) ? ((const float4*)b_mu)[lane]
                           : ((const float4*)b_ls)[lane - 16];
    float4 v;
    v.x = a.x * dinv + b.x;
    v.y = a.y * dinv + b.y;
    v.z = a.z * dinv + b.z;
    v.w = a.w * dinv + b.w;

    // exp(min(ls,10)) — meaningful on lanes 16-31; harmless elsewhere (capped)
    float px = expf(fminf(v.x, MAX_LOGSTD));
    float py = expf(fminf(v.y, MAX_LOGSTD));
    float pz = expf(fminf(v.z, MAX_LOGSTD));
    float pw = expf(fminf(v.w, MAX_LOGSTD));
    px = __shfl_down_sync(0xFFFFFFFFu, px, 16);
    py = __shfl_down_sync(0xFFFFFFFFu, py, 16);
    pz = __shfl_down_sync(0xFFFFFFFFu, pz, 16);
    pw = __shfl_down_sync(0xFFFFFFFFu, pw, 16);

    if (lane < 16) {
        float4 e4 = ((const float4*)(eps + (size_t)node * COUT))[lane];
        float4 z;
        z.x = v.x + e4.x * px;
        z.y = v.y + e4.y * py;
        z.z = v.z + e4.z * pz;
        z.w = v.w + e4.w * pw;
        ((float4*)(out + (size_t)node * COUT))[lane] = z;
    }
}

extern "C" void kernel_launch(void* const* d_in, const int* in_sizes, int n_in,
                              void* d_out, int out_size)
{
    const float* x   = (const float*)d_in[0];
    const void*  ei  = d_in[1];                 // int32 or int64, detected on device
    const float* Wmu = (const float*)d_in[2];
    const float* bmu = (const float*)d_in[3];
    const float* Wls = (const float*)d_in[4];
    const float* bls = (const float*)d_in[5];
    const float* eps = (const float*)d_in[6];
    float*       out = (float*)d_out;

    int N = in_sizes[0] / CIN;          // 100000
    long long E = in_sizes[1] / 2;      // 1600000

    zero_kernel<<<(N + 255) / 256, 256>>>(N);
    detect_kernel<<<(int)((E + 255) / 256), 256>>>((const long long*)ei, E, N);
    count_kernel<<<(int)((E + 255) / 256), 256>>>(ei, E, N);
    scan_kernel<<<1, 1024>>>(N);
    fill_kernel<<<(int)((E + 255) / 256), 256>>>(ei, E, N);
    gemm_kernel<<<(N + 63) / 64, 256>>>(x, Wmu, Wls, N);
    gather_kernel<<<(N + 7) / 8, 256>>>(bmu, bls, eps, out, N);
}

// round 6
// speedup vs baseline: 2.7540x; 1.8502x over previous
#include <cuda_runtime.h>

#define CIN  128
#define CTOT 128   // [mu(64) | logstd(64)]
#define COUT 64
#define NMAX 100000
#define EMAX 2000000
#define MAX_LOGSTD 10.0f

// Scratch (device globals: no allocations allowed)
__device__ float g_feat[(size_t)NMAX * CTOT];  // g = (x @ [Wmu|Wls]) * dinv[row]
__device__ int   g_cnt [NMAX];                 // in-degree (without self-loop)
__device__ int   g_beg [NMAX];                 // CSR segment start (atomic alloc)
__device__ int   g_cur [NMAX];                 // fill cursors
__device__ int   g_srcs[EMAX];                 // CSR column (src) indices
__device__ int   g_ctr;                        // global allocation cursor
__device__ int   g_is64;                       // 1 if edge_index really is int64

// ---------------------------------------------------------------------------
// 0) zero counts + reset cursor + dtype flag (deterministic across replays)
__global__ void zero_kernel(int N) {
    int i = blockIdx.x * blockDim.x + threadIdx.x;
    if (i < N) g_cnt[i] = 0;
    if (i == 0) { g_is64 = 1; g_ctr = 0; }
}

// 0b) dtype detect: read first E slots AS int64 (first 8E bytes; buffer holds
//     >= 8E bytes under either dtype -> never OOB). Any value outside [0,N)
//     means the data cannot be int64 node indices.
__global__ void detect_kernel(const long long* __restrict__ ei, long long E, int N) {
    long long i = (long long)blockIdx.x * blockDim.x + threadIdx.x;
    if (i < E) {
        long long v = ei[i];
        if (v < 0 || v >= N) g_is64 = 0;   // racy same-value write: fine
    }
}

__device__ __forceinline__ int load_idx(const void* ei, long long slot) {
    return g_is64 ? (int)((const long long*)ei)[slot]
                  : ((const int*)ei)[slot];
}

// 1) in-degree count over dst
__global__ void count_kernel(const void* __restrict__ ei, long long E, int N) {
    long long i = (long long)blockIdx.x * blockDim.x + threadIdx.x;
    if (i < E) {
        int dst = load_idx(ei, E + i);
        if ((unsigned)dst < (unsigned)N) atomicAdd(&g_cnt[dst], 1);
    }
}

// 2) CSR segment allocation: order-free replacement for the exclusive scan.
//    Uniform-address atomicAdd -> ptxas warp-aggregates (REDUX + 1 ATOMS/warp).
__global__ void alloc_kernel(int N) {
    int i = blockIdx.x * blockDim.x + threadIdx.x;
    if (i < N) {
        int c = g_cnt[i];
        int beg = atomicAdd(&g_ctr, c);
        g_beg[i] = beg;
        g_cur[i] = beg;
    }
}

// 3) CSR fill: scatter src indices into dst-grouped segments
__global__ void fill_kernel(const void* __restrict__ ei, long long E, int N) {
    long long i = (long long)blockIdx.x * blockDim.x + threadIdx.x;
    if (i < E) {
        int src = load_idx(ei, i);
        int dst = load_idx(ei, E + i);
        if ((unsigned)src < (unsigned)N && (unsigned)dst < (unsigned)N) {
            int pos = atomicAdd(&g_cur[dst], 1);
            if (pos < EMAX) g_srcs[pos] = src;
        }
    }
}

// ---------------------------------------------------------------------------
// packed fp32x2 helpers (sm_100+: SASS FFMA2, 2 fp32 FMAs per issue slot)
__device__ __forceinline__ unsigned long long fma_x2(unsigned long long a,
                                                     unsigned long long b,
                                                     unsigned long long c) {
    unsigned long long d;
    asm("fma.rn.f32x2 %0, %1, %2, %3;" : "=l"(d) : "l"(a), "l"(b), "l"(c));
    return d;
}
__device__ __forceinline__ unsigned long long bcast_x2(float x) {
    unsigned long long d;
    asm("mov.b64 %0, {%1, %1};" : "=l"(d) : "r"(__float_as_uint(x)));
    return d;
}
__device__ __forceinline__ float2 unpack_x2(unsigned long long v) {
    unsigned int lo, hi;
    asm("mov.b64 {%0, %1}, %2;" : "=r"(lo), "=r"(hi) : "l"(v));
    return make_float2(__uint_as_float(lo), __uint_as_float(hi));
}

// 4) GEMM: g_feat[row] = (x[row] @ [Wmu|Wls]) * rsqrt(deg[row])
//    BM=64, BN=128(full), BK=32. 256 threads, each computes 4 rows x 8 cols,
//    inner product via fma.rn.f32x2 (16 FFMA2 + 4 MOV per k-step vs 32 FFMA).
__global__ __launch_bounds__(256) void gemm_kernel(
    const float* __restrict__ x,
    const float* __restrict__ Wmu,
    const float* __restrict__ Wls,
    int N)
{
    __shared__ float w_s[32 * 128];   // [k_local][c]
    __shared__ float x_s[32 * 68];    // [k_local][row] padded 64->68 (16B-aligned rows)

    const int tid  = threadIdx.x;
    const int row0 = blockIdx.x * 64;
    const int ty   = tid >> 4;
    const int tx   = tid & 15;
    const int r0   = ty * 4;

    unsigned long long accp[4][4];
    #pragma unroll
    for (int i = 0; i < 4; i++)
        #pragma unroll
        for (int j = 0; j < 4; j++) accp[i][j] = 0ULL;

    for (int kt = 0; kt < 4; kt++) {
        #pragma unroll
        for (int j = 0; j < 16; j++) {
            int idx = tid + j * 256;
            int kl = idx >> 7, c = idx & 127;
            int k = kt * 32 + kl;
            w_s[idx] = (c < 64) ? Wmu[k * 64 + c] : Wls[k * 64 + (c - 64)];
        }
        #pragma unroll
        for (int j = 0; j < 8; j++) {
            int idx = tid + j * 256;
            int r = idx >> 5, kl = idx & 31;
            int row = row0 + r;
            float v = (row < N) ? x[(size_t)row * CIN + kt * 32 + kl] : 0.0f;
            x_s[kl * 68 + r] = v;
        }
        __syncthreads();

        #pragma unroll
        for (int kl = 0; kl < 32; kl++) {
            float4 xa = *(const float4*)&x_s[kl * 68 + r0];
            ulonglong2 w0 = *(const ulonglong2*)&w_s[kl * 128 + tx * 4];
            ulonglong2 w1 = *(const ulonglong2*)&w_s[kl * 128 + 64 + tx * 4];
            unsigned long long wp[4] = {w0.x, w0.y, w1.x, w1.y};
            float xr[4] = {xa.x, xa.y, xa.z, xa.w};
            #pragma unroll
            for (int i = 0; i < 4; i++) {
                unsigned long long xp = bcast_x2(xr[i]);
                #pragma unroll
                for (int j = 0; j < 4; j++)
                    accp[i][j] = fma_x2(xp, wp[j], accp[i][j]);
            }
        }
        __syncthreads();
    }

    #pragma unroll
    for (int i = 0; i < 4; i++) {
        int row = row0 + r0 + i;
        if (row >= N) continue;
        float dinv = rsqrtf((float)g_cnt[row] + 1.0f);
        float2 p0 = unpack_x2(accp[i][0]);
        float2 p1 = unpack_x2(accp[i][1]);
        float2 p2 = unpack_x2(accp[i][2]);
        float2 p3 = unpack_x2(accp[i][3]);
        float4 va = make_float4(p0.x * dinv, p0.y * dinv, p1.x * dinv, p1.y * dinv);
        float4 vb = make_float4(p2.x * dinv, p2.y * dinv, p3.x * dinv, p3.y * dinv);
        size_t base = (size_t)row * CTOT;
        *(float4*)&g_feat[base + tx * 4]      = va;
        *(float4*)&g_feat[base + 64 + tx * 4] = vb;
    }
}

// 5) fused gather + finalize: one warp per node. Lane l owns float4 features
//    [4l, 4l+4) of the 128-wide fused row (lanes 0-15 = mu, 16-31 = logstd).
__global__ __launch_bounds__(256) void gather_kernel(
    const float* __restrict__ b_mu,
    const float* __restrict__ b_ls,
    const float* __restrict__ eps,
    float* __restrict__ out,
    int N)
{
    int node = blockIdx.x * 8 + (threadIdx.x >> 5);
    if (node >= N) return;
    int lane = threadIdx.x & 31;

    int cnt = g_cnt[node];
    int beg = g_beg[node];
    int end = beg + cnt;

    float4 a = ((const float4*)(g_feat + (size_t)node * CTOT))[lane];  // self-loop

    int e = beg;
    for (; e + 8 <= end; e += 8) {       // unroll 8 for MLP
        int s[8];
        #pragma unroll
        for (int u = 0; u < 8; u++) s[u] = g_srcs[e + u];
        float4 v[8];
        #pragma unroll
        for (int u = 0; u < 8; u++)
            v[u] = ((const float4*)(g_feat + (size_t)s[u] * CTOT))[lane];
        #pragma unroll
        for (int u = 0; u < 8; u++) {
            a.x += v[u].x; a.y += v[u].y; a.z += v[u].z; a.w += v[u].w;
        }
    }
    for (; e < end; e++) {
        int sidx = g_srcs[e];
        float4 v = ((const float4*)(g_feat + (size_t)sidx * CTOT))[lane];
        a.x += v.x; a.y += v.y; a.z += v.z; a.w += v.w;
    }

    float dinv = rsqrtf((float)cnt + 1.0f);
    float4 b = (lane < 16) ? ((const float4*)b_mu)[lane]
                           : ((const float4*)b_ls)[lane - 16];
    float4 v;
    v.x = a.x * dinv + b.x;
    v.y = a.y * dinv + b.y;
    v.z = a.z * dinv + b.z;
    v.w = a.w * dinv + b.w;

    // exp(min(ls,10)) — meaningful on lanes 16-31; harmless elsewhere (capped)
    float px = expf(fminf(v.x, MAX_LOGSTD));
    float py = expf(fminf(v.y, MAX_LOGSTD));
    float pz = expf(fminf(v.z, MAX_LOGSTD));
    float pw = expf(fminf(v.w, MAX_LOGSTD));
    px = __shfl_down_sync(0xFFFFFFFFu, px, 16);
    py = __shfl_down_sync(0xFFFFFFFFu, py, 16);
    pz = __shfl_down_sync(0xFFFFFFFFu, pz, 16);
    pw = __shfl_down_sync(0xFFFFFFFFu, pw, 16);

    if (lane < 16) {
        float4 e4 = ((const float4*)(eps + (size_t)node * COUT))[lane];
        float4 z;
        z.x = v.x + e4.x * px;
        z.y = v.y + e4.y * py;
        z.z = v.z + e4.z * pz;
        z.w = v.w + e4.w * pw;
        ((float4*)(out + (size_t)node * COUT))[lane] = z;
    }
}

extern "C" void kernel_launch(void* const* d_in, const int* in_sizes, int n_in,
                              void* d_out, int out_size)
{
    const float* x   = (const float*)d_in[0];
    const void*  ei  = d_in[1];                 // int32 or int64, detected on device
    const float* Wmu = (const float*)d_in[2];
    const float* bmu = (const float*)d_in[3];
    const float* Wls = (const float*)d_in[4];
    const float* bls = (const float*)d_in[5];
    const float* eps = (const float*)d_in[6];
    float*       out = (float*)d_out;

    int N = in_sizes[0] / CIN;          // 100000
    long long E = in_sizes[1] / 2;      // 1600000

    zero_kernel<<<(N + 255) / 256, 256>>>(N);
    detect_kernel<<<(int)((E + 255) / 256), 256>>>((const long long*)ei, E, N);
    count_kernel<<<(int)((E + 255) / 256), 256>>>(ei, E, N);
    alloc_kernel<<<(N + 255) / 256, 256>>>(N);
    fill_kernel<<<(int)((E + 255) / 256), 256>>>(ei, E, N);
    gemm_kernel<<<(N + 63) / 64, 256>>>(x, Wmu, Wls, N);
    gather_kernel<<<(N + 7) / 8, 256>>>(bmu, bls, eps, out, N);
}

// round 8
// speedup vs baseline: 3.2153x; 1.1675x over previous
#include <cuda_runtime.h>
#include <cuda_fp16.h>

#define CIN  128
#define CTOT 128   // [mu(64) | logstd(64)]
#define COUT 64
#define NMAX 100000
#define EMAX 2000000
#define MAX_LOGSTD 10.0f

// Scratch (device globals: no allocations allowed)
// g_feat in fp16: row = 128 halves = 256B = 32 lanes x 8B (uint2)
__device__ __align__(16) __half g_feat[(size_t)NMAX * CTOT];
__device__ int   g_cnt [NMAX];                 // in-degree (without self-loop)
__device__ int   g_beg [NMAX];                 // CSR segment start (atomic alloc)
__device__ int   g_cur [NMAX];                 // fill cursors
__device__ int   g_srcs[EMAX];                 // CSR column (src) indices
__device__ int   g_ctr;                        // global allocation cursor
__device__ int   g_is64;                       // 1 if edge_index really is int64

// ---------------------------------------------------------------------------
// 0) zero counts + reset cursor + dtype flag (deterministic across replays)
__global__ void zero_kernel(int N) {
    int i = blockIdx.x * blockDim.x + threadIdx.x;
    if (i < N) g_cnt[i] = 0;
    if (i == 0) { g_is64 = 1; g_ctr = 0; }
}

// 0b) dtype detect (sampled): read first min(E,64K) slots AS int64 (first 8*cap
//     bytes; buffer holds >= 8*cap under either dtype -> never OOB). An int32
//     pair misread as int64 passes the [0,N) test only if the high word is 0
//     (p ~ 1e-5 per slot) -> 64K samples decide with certainty.
__global__ void detect_kernel(const long long* __restrict__ ei, long long cap, int N) {
    long long i = (long long)blockIdx.x * blockDim.x + threadIdx.x;
    if (i < cap) {
        long long v = ei[i];
        if (v < 0 || v >= N) g_is64 = 0;   // racy same-value write: fine
    }
}

__device__ __forceinline__ int load_idx(const void* ei, long long slot) {
    return g_is64 ? (int)((const long long*)ei)[slot]
                  : ((const int*)ei)[slot];
}

// 1) in-degree count over dst
__global__ void count_kernel(const void* __restrict__ ei, long long E, int N) {
    long long i = (long long)blockIdx.x * blockDim.x + threadIdx.x;
    if (i < E) {
        int dst = load_idx(ei, E + i);
        if ((unsigned)dst < (unsigned)N) atomicAdd(&g_cnt[dst], 1);
    }
}

// 2) CSR segment allocation: order-free replacement for an exclusive scan.
//    Uniform-address atomicAdd -> ptxas warp-aggregates (REDUX + 1 ATOMS/warp).
__global__ void alloc_kernel(int N) {
    int i = blockIdx.x * blockDim.x + threadIdx.x;
    if (i < N) {
        int c = g_cnt[i];
        int beg = atomicAdd(&g_ctr, c);
        g_beg[i] = beg;
        g_cur[i] = beg;
    }
}

// 3) CSR fill: scatter src indices into dst-grouped segments
__global__ void fill_kernel(const void* __restrict__ ei, long long E, int N) {
    long long i = (long long)blockIdx.x * blockDim.x + threadIdx.x;
    if (i < E) {
        int src = load_idx(ei, i);
        int dst = load_idx(ei, E + i);
        if ((unsigned)src < (unsigned)N && (unsigned)dst < (unsigned)N) {
            int pos = atomicAdd(&g_cur[dst], 1);
            if (pos < EMAX) g_srcs[pos] = src;
        }
    }
}

// ---------------------------------------------------------------------------
// packed fp32x2 helpers (sm_100+: SASS FFMA2, 2 fp32 FMAs per issue slot)
__device__ __forceinline__ unsigned long long fma_x2(unsigned long long a,
                                                     unsigned long long b,
                                                     unsigned long long c) {
    unsigned long long d;
    asm("fma.rn.f32x2 %0, %1, %2, %3;" : "=l"(d) : "l"(a), "l"(b), "l"(c));
    return d;
}
__device__ __forceinline__ unsigned long long bcast_x2(float x) {
    unsigned long long d;
    asm("mov.b64 %0, {%1, %1};" : "=l"(d) : "r"(__float_as_uint(x)));
    return d;
}
__device__ __forceinline__ float2 unpack_x2(unsigned long long v) {
    unsigned int lo, hi;
    asm("mov.b64 {%0, %1}, %2;" : "=r"(lo), "=r"(hi) : "l"(v));
    return make_float2(__uint_as_float(lo), __uint_as_float(hi));
}

// 4) GEMM: g_feat[row] = fp16( (x[row] @ [Wmu|Wls]) * rsqrt(deg[row]) )
//    BM=64, BN=128(full), BK=32. 256 threads, each computes 4 rows x 8 cols,
//    inner product via fma.rn.f32x2.
__global__ __launch_bounds__(256) void gemm_kernel(
    const float* __restrict__ x,
    const float* __restrict__ Wmu,
    const float* __restrict__ Wls,
    int N)
{
    __shared__ float w_s[32 * 128];   // [k_local][c]
    __shared__ float x_s[32 * 68];    // [k_local][row] padded 64->68

    const int tid  = threadIdx.x;
    const int row0 = blockIdx.x * 64;
    const int ty   = tid >> 4;
    const int tx   = tid & 15;
    const int r0   = ty * 4;

    unsigned long long accp[4][4];
    #pragma unroll
    for (int i = 0; i < 4; i++)
        #pragma unroll
        for (int j = 0; j < 4; j++) accp[i][j] = 0ULL;

    for (int kt = 0; kt < 4; kt++) {
        #pragma unroll
        for (int j = 0; j < 16; j++) {
            int idx = tid + j * 256;
            int kl = idx >> 7, c = idx & 127;
            int k = kt * 32 + kl;
            w_s[idx] = (c < 64) ? Wmu[k * 64 + c] : Wls[k * 64 + (c - 64)];
        }
        #pragma unroll
        for (int j = 0; j < 8; j++) {
            int idx = tid + j * 256;
            int r = idx >> 5, kl = idx & 31;
            int row = row0 + r;
            float v = (row < N) ? x[(size_t)row * CIN + kt * 32 + kl] : 0.0f;
            x_s[kl * 68 + r] = v;
        }
        __syncthreads();

        #pragma unroll
        for (int kl = 0; kl < 32; kl++) {
            float4 xa = *(const float4*)&x_s[kl * 68 + r0];
            ulonglong2 w0 = *(const ulonglong2*)&w_s[kl * 128 + tx * 4];
            ulonglong2 w1 = *(const ulonglong2*)&w_s[kl * 128 + 64 + tx * 4];
            unsigned long long wp[4] = {w0.x, w0.y, w1.x, w1.y};
            float xr[4] = {xa.x, xa.y, xa.z, xa.w};
            #pragma unroll
            for (int i = 0; i < 4; i++) {
                unsigned long long xp = bcast_x2(xr[i]);
                #pragma unroll
                for (int j = 0; j < 4; j++)
                    accp[i][j] = fma_x2(xp, wp[j], accp[i][j]);
            }
        }
        __syncthreads();
    }

    #pragma unroll
    for (int i = 0; i < 4; i++) {
        int row = row0 + r0 + i;
        if (row >= N) continue;
        float dinv = rsqrtf((float)g_cnt[row] + 1.0f);
        float2 p0 = unpack_x2(accp[i][0]);
        float2 p1 = unpack_x2(accp[i][1]);
        float2 p2 = unpack_x2(accp[i][2]);
        float2 p3 = unpack_x2(accp[i][3]);
        __half2 h0 = __float22half2_rn(make_float2(p0.x * dinv, p0.y * dinv));
        __half2 h1 = __float22half2_rn(make_float2(p1.x * dinv, p1.y * dinv));
        __half2 h2 = __float22half2_rn(make_float2(p2.x * dinv, p2.y * dinv));
        __half2 h3 = __float22half2_rn(make_float2(p3.x * dinv, p3.y * dinv));
        uint2 wa, wb;
        wa.x = *(unsigned*)&h0;  wa.y = *(unsigned*)&h1;
        wb.x = *(unsigned*)&h2;  wb.y = *(unsigned*)&h3;
        uint2* rowp = (uint2*)(g_feat + (size_t)row * CTOT);
        rowp[tx]      = wa;   // mu half: halves [tx*4, tx*4+4)
        rowp[16 + tx] = wb;   // ls half: halves [64+tx*4, ...)
    }
}

// 5) fused gather + finalize: one warp per node. Lane l owns 4 fp16 features
//    [4l, 4l+4) (one uint2 = 8B) of the 256B row. Lanes 0-15 = mu, 16-31 = ls.
__global__ __launch_bounds__(256) void gather_kernel(
    const float* __restrict__ b_mu,
    const float* __restrict__ b_ls,
    const float* __restrict__ eps,
    float* __restrict__ out,
    int N)
{
    int node = blockIdx.x * 8 + (threadIdx.x >> 5);
    if (node >= N) return;
    int lane = threadIdx.x & 31;

    int cnt = g_cnt[node];
    int beg = g_beg[node];
    int end = beg + cnt;

    // self-loop
    uint2 r0 = ((const uint2*)(g_feat + (size_t)node * CTOT))[lane];
    float2 f0 = __half22float2(*(__half2*)&r0.x);
    float2 f1 = __half22float2(*(__half2*)&r0.y);
    float4 a = make_float4(f0.x, f0.y, f1.x, f1.y);

    int e = beg;
    for (; e + 8 <= end; e += 8) {       // unroll 8 for MLP
        int s[8];
        #pragma unroll
        for (int u = 0; u < 8; u++) s[u] = g_srcs[e + u];
        uint2 v[8];
        #pragma unroll
        for (int u = 0; u < 8; u++)
            v[u] = ((const uint2*)(g_feat + (size_t)s[u] * CTOT))[lane];
        #pragma unroll
        for (int u = 0; u < 8; u++) {
            float2 g0 = __half22float2(*(__half2*)&v[u].x);
            float2 g1 = __half22float2(*(__half2*)&v[u].y);
            a.x += g0.x; a.y += g0.y; a.z += g1.x; a.w += g1.y;
        }
    }
    for (; e < end; e++) {
        int sidx = g_srcs[e];
        uint2 vv = ((const uint2*)(g_feat + (size_t)sidx * CTOT))[lane];
        float2 g0 = __half22float2(*(__half2*)&vv.x);
        float2 g1 = __half22float2(*(__half2*)&vv.y);
        a.x += g0.x; a.y += g0.y; a.z += g1.x; a.w += g1.y;
    }

    float dinv = rsqrtf((float)cnt + 1.0f);
    float4 b = (lane < 16) ? ((const float4*)b_mu)[lane]
                           : ((const float4*)b_ls)[lane - 16];
    float4 v;
    v.x = a.x * dinv + b.x;
    v.y = a.y * dinv + b.y;
    v.z = a.z * dinv + b.z;
    v.w = a.w * dinv + b.w;

    // exp(min(ls,10)) — meaningful on lanes 16-31; harmless elsewhere (capped)
    float px = expf(fminf(v.x, MAX_LOGSTD));
    float py = expf(fminf(v.y, MAX_LOGSTD));
    float pz = expf(fminf(v.z, MAX_LOGSTD));
    float pw = expf(fminf(v.w, MAX_LOGSTD));
    px = __shfl_down_sync(0xFFFFFFFFu, px, 16);
    py = __shfl_down_sync(0xFFFFFFFFu, py, 16);
    pz = __shfl_down_sync(0xFFFFFFFFu, pz, 16);
    pw = __shfl_down_sync(0xFFFFFFFFu, pw, 16);

    if (lane < 16) {
        float4 e4 = ((const float4*)(eps + (size_t)node * COUT))[lane];
        float4 z;
        z.x = v.x + e4.x * px;
        z.y = v.y + e4.y * py;
        z.z = v.z + e4.z * pz;
        z.w = v.w + e4.w * pw;
        ((float4*)(out + (size_t)node * COUT))[lane] = z;
    }
}

extern "C" void kernel_launch(void* const* d_in, const int* in_sizes, int n_in,
                              void* d_out, int out_size)
{
    const float* x   = (const float*)d_in[0];
    const void*  ei  = d_in[1];                 // int32 or int64, detected on device
    const float* Wmu = (const float*)d_in[2];
    const float* bmu = (const float*)d_in[3];
    const float* Wls = (const float*)d_in[4];
    const float* bls = (const float*)d_in[5];
    const float* eps = (const float*)d_in[6];
    float*       out = (float*)d_out;

    int N = in_sizes[0] / CIN;          // 100000
    long long E = in_sizes[1] / 2;      // 1600000
    long long cap = E < 65536 ? E : 65536;

    zero_kernel<<<(N + 255) / 256, 256>>>(N);
    detect_kernel<<<(int)((cap + 255) / 256), 256>>>((const long long*)ei, cap, N);
    count_kernel<<<(int)((E + 255) / 256), 256>>>(ei, E, N);
    alloc_kernel<<<(N + 255) / 256, 256>>>(N);
    fill_kernel<<<(int)((E + 255) / 256), 256>>>(ei, E, N);
    gemm_kernel<<<(N + 63) / 64, 256>>>(x, Wmu, Wls, N);
    gather_kernel<<<(N + 7) / 8, 256>>>(bmu, bls, eps, out, N);
}

// round 9
// speedup vs baseline: 4.6048x; 1.4321x over previous
#include <cuda_runtime.h>
#include <cuda_fp16.h>

#define CIN  128
#define CTOT 128   // [mu(64) | logstd(64)]
#define COUT 64
#define NMAX 100000
#define EMAX 2000000
#define MAX_LOGSTD 10.0f

#define XPAD 136   // halves per padded smem row (68 words == 4 mod 32: conflict-free frags)
#define GEMM_SMEM ((64 + 128) * XPAD * 2)

// Scratch (device globals: no allocations allowed)
// g_feat in fp16: row = 128 halves = 256B = 32 lanes x 8B (uint2)
__device__ __align__(16) __half g_feat[(size_t)NMAX * CTOT];
__device__ int   g_cnt [NMAX];                 // in-degree (without self-loop)
__device__ int   g_beg [NMAX];                 // CSR segment start (atomic alloc)
__device__ int   g_cur [NMAX];                 // fill cursors
__device__ int   g_srcs[EMAX];                 // CSR column (src) indices
__device__ int   g_ctr;                        // global allocation cursor
__device__ int   g_is64;                       // 1 if edge_index really is int64

// ---------------------------------------------------------------------------
// 0) zero counts + reset cursor + dtype flag (deterministic across replays)
__global__ void zero_kernel(int N) {
    int i = blockIdx.x * blockDim.x + threadIdx.x;
    if (i < N) g_cnt[i] = 0;
    if (i == 0) { g_is64 = 1; g_ctr = 0; }
}

// 0b) dtype detect (sampled): read first min(E,64K) slots AS int64 (never OOB
//     under either dtype). Misread-int32 passes [0,N) only if its high word
//     is 0 (p ~ 1e-5/slot) -> 64K samples decide with certainty.
__global__ void detect_kernel(const long long* __restrict__ ei, long long cap, int N) {
    long long i = (long long)blockIdx.x * blockDim.x + threadIdx.x;
    if (i < cap) {
        long long v = ei[i];
        if (v < 0 || v >= N) g_is64 = 0;   // racy same-value write: fine
    }
}

__device__ __forceinline__ int load_idx(const void* ei, long long slot) {
    return g_is64 ? (int)((const long long*)ei)[slot]
                  : ((const int*)ei)[slot];
}

// 1) in-degree count over dst
__global__ void count_kernel(const void* __restrict__ ei, long long E, int N) {
    long long i = (long long)blockIdx.x * blockDim.x + threadIdx.x;
    if (i < E) {
        int dst = load_idx(ei, E + i);
        if ((unsigned)dst < (unsigned)N) atomicAdd(&g_cnt[dst], 1);
    }
}

// 2) CSR segment allocation (order-free scan replacement; warp-aggregated atomic)
__global__ void alloc_kernel(int N) {
    int i = blockIdx.x * blockDim.x + threadIdx.x;
    if (i < N) {
        int c = g_cnt[i];
        int beg = atomicAdd(&g_ctr, c);
        g_beg[i] = beg;
        g_cur[i] = beg;
    }
}

// 3) CSR fill: scatter src indices into dst-grouped segments
__global__ void fill_kernel(const void* __restrict__ ei, long long E, int N) {
    long long i = (long long)blockIdx.x * blockDim.x + threadIdx.x;
    if (i < E) {
        int src = load_idx(ei, i);
        int dst = load_idx(ei, E + i);
        if ((unsigned)src < (unsigned)N && (unsigned)dst < (unsigned)N) {
            int pos = atomicAdd(&g_cur[dst], 1);
            if (pos < EMAX) g_srcs[pos] = src;
        }
    }
}

// 4) Tensor-core GEMM: g_feat[row] = fp16( (x[row] @ [Wmu|Wls]) * dinv[row] )
//    BM=64, BN=128(full), K=128(full). 256 threads = 8 warps in 4(M)x2(N).
//    Each warp: 16 rows x 64 cols via 8x8 mma.sync.m16n8k16 (fp16 in, fp32 acc).
//    x_s row-major [64][XPAD], w_s transposed [c][k] = [128][XPAD]: direct 4B
//    LDS fragment loads, conflict-free by the XPAD bank offset.
__global__ __launch_bounds__(256) void gemm_kernel(
    const float* __restrict__ x,
    const float* __restrict__ Wmu,
    const float* __restrict__ Wls,
    int N)
{
    extern __shared__ __half sh[];
    __half* x_s = sh;              // [64][XPAD]
    __half* w_s = sh + 64 * XPAD;  // [128][XPAD]

    const int tid  = threadIdx.x;
    const int row0 = blockIdx.x * 64;

    // stage x (fp32->fp16), coalesced over k
    #pragma unroll
    for (int j = 0; j < 32; j++) {
        int idx = tid + j * 256;          // 8192 = 64*128
        int r = idx >> 7, k = idx & 127;
        int row = row0 + r;
        float v = (row < N) ? x[(size_t)row * CIN + k] : 0.0f;
        x_s[r * XPAD + k] = __float2half_rn(v);
    }
    // stage W transposed: w_s[c][k] <- [Wmu|Wls][k][c], coalesced global read
    #pragma unroll
    for (int j = 0; j < 64; j++) {
        int idx = tid + j * 256;          // 16384 = 128*128
        int k = idx >> 7, c = idx & 127;
        float v = (c < 64) ? Wmu[k * 64 + c] : Wls[k * 64 + (c - 64)];
        w_s[c * XPAD + k] = __float2half_rn(v);
    }
    __syncthreads();

    const int w    = tid >> 5;
    const int lane = tid & 31;
    const int wr   = w & 3;          // row block  (16 rows)
    const int wc   = w >> 2;         // col block  (64 cols)
    const int g    = lane >> 2;      // group row
    const int t    = lane & 3;       // k-pair / col-pair selector

    float acc[8][4];
    #pragma unroll
    for (int nt = 0; nt < 8; nt++)
        #pragma unroll
        for (int q = 0; q < 4; q++) acc[nt][q] = 0.0f;

    const __half* xb = x_s + (wr * 16 + g) * XPAD + t * 2;
    const __half* wb = w_s + (wc * 64 + g) * XPAD + t * 2;

    #pragma unroll
    for (int kc = 0; kc < 8; kc++) {
        unsigned a0 = *(const unsigned*)(xb + kc * 16);
        unsigned a1 = *(const unsigned*)(xb + kc * 16 + 8 * XPAD);
        unsigned a2 = *(const unsigned*)(xb + kc * 16 + 8);
        unsigned a3 = *(const unsigned*)(xb + kc * 16 + 8 * XPAD + 8);
        #pragma unroll
        for (int nt = 0; nt < 8; nt++) {
            unsigned b0 = *(const unsigned*)(wb + nt * 8 * XPAD + kc * 16);
            unsigned b1 = *(const unsigned*)(wb + nt * 8 * XPAD + kc * 16 + 8);
            asm volatile(
                "mma.sync.aligned.m16n8k16.row.col.f32.f16.f16.f32 "
                "{%0,%1,%2,%3}, {%4,%5,%6,%7}, {%8,%9}, {%0,%1,%2,%3};"
                : "+f"(acc[nt][0]), "+f"(acc[nt][1]),
                  "+f"(acc[nt][2]), "+f"(acc[nt][3])
                : "r"(a0), "r"(a1), "r"(a2), "r"(a3), "r"(b0), "r"(b1));
        }
    }

    // epilogue: * dinv, pack fp16.  c0,c1 -> row g cols t*2,t*2+1; c2,c3 -> row g+8
    int r1 = row0 + wr * 16 + g;
    int r2 = r1 + 8;
    float d1 = (r1 < N) ? rsqrtf((float)g_cnt[r1] + 1.0f) : 0.0f;
    float d2 = (r2 < N) ? rsqrtf((float)g_cnt[r2] + 1.0f) : 0.0f;
    #pragma unroll
    for (int nt = 0; nt < 8; nt++) {
        int col = wc * 64 + nt * 8 + t * 2;
        if (r1 < N) {
            __half2 h = __floats2half2_rn(acc[nt][0] * d1, acc[nt][1] * d1);
            *(__half2*)(g_feat + (size_t)r1 * CTOT + col) = h;
        }
        if (r2 < N) {
            __half2 h = __floats2half2_rn(acc[nt][2] * d2, acc[nt][3] * d2);
            *(__half2*)(g_feat + (size_t)r2 * CTOT + col) = h;
        }
    }
}

// 5) fused gather + finalize: one warp per node. Lane l owns 4 fp16 features
//    [4l, 4l+4) (one uint2 = 8B) of the 256B row. Lanes 0-15 = mu, 16-31 = ls.
__global__ __launch_bounds__(256) void gather_kernel(
    const float* __restrict__ b_mu,
    const float* __restrict__ b_ls,
    const float* __restrict__ eps,
    float* __restrict__ out,
    int N)
{
    int node = blockIdx.x * 8 + (threadIdx.x >> 5);
    if (node >= N) return;
    int lane = threadIdx.x & 31;

    int cnt = g_cnt[node];
    int beg = g_beg[node];
    int end = beg + cnt;

    // self-loop
    uint2 r0 = ((const uint2*)(g_feat + (size_t)node * CTOT))[lane];
    float2 f0 = __half22float2(*(__half2*)&r0.x);
    float2 f1 = __half22float2(*(__half2*)&r0.y);
    float4 a = make_float4(f0.x, f0.y, f1.x, f1.y);

    int e = beg;
    for (; e + 8 <= end; e += 8) {       // unroll 8 for MLP
        int s[8];
        #pragma unroll
        for (int u = 0; u < 8; u++) s[u] = g_srcs[e + u];
        uint2 v[8];
        #pragma unroll
        for (int u = 0; u < 8; u++)
            v[u] = ((const uint2*)(g_feat + (size_t)s[u] * CTOT))[lane];
        #pragma unroll
        for (int u = 0; u < 8; u++) {
            float2 g0 = __half22float2(*(__half2*)&v[u].x);
            float2 g1 = __half22float2(*(__half2*)&v[u].y);
            a.x += g0.x; a.y += g0.y; a.z += g1.x; a.w += g1.y;
        }
    }
    for (; e < end; e++) {
        int sidx = g_srcs[e];
        uint2 vv = ((const uint2*)(g_feat + (size_t)sidx * CTOT))[lane];
        float2 g0 = __half22float2(*(__half2*)&vv.x);
        float2 g1 = __half22float2(*(__half2*)&vv.y);
        a.x += g0.x; a.y += g0.y; a.z += g1.x; a.w += g1.y;
    }

    float dinv = rsqrtf((float)cnt + 1.0f);
    float4 b = (lane < 16) ? ((const float4*)b_mu)[lane]
                           : ((const float4*)b_ls)[lane - 16];
    float4 v;
    v.x = a.x * dinv + b.x;
    v.y = a.y * dinv + b.y;
    v.z = a.z * dinv + b.z;
    v.w = a.w * dinv + b.w;

    // exp(min(ls,10)) — meaningful on lanes 16-31; harmless elsewhere (capped)
    float px = expf(fminf(v.x, MAX_LOGSTD));
    float py = expf(fminf(v.y, MAX_LOGSTD));
    float pz = expf(fminf(v.z, MAX_LOGSTD));
    float pw = expf(fminf(v.w, MAX_LOGSTD));
    px = __shfl_down_sync(0xFFFFFFFFu, px, 16);
    py = __shfl_down_sync(0xFFFFFFFFu, py, 16);
    pz = __shfl_down_sync(0xFFFFFFFFu, pz, 16);
    pw = __shfl_down_sync(0xFFFFFFFFu, pw, 16);

    if (lane < 16) {
        float4 e4 = ((const float4*)(eps + (size_t)node * COUT))[lane];
        float4 z;
        z.x = v.x + e4.x * px;
        z.y = v.y + e4.y * py;
        z.z = v.z + e4.z * pz;
        z.w = v.w + e4.w * pw;
        ((float4*)(out + (size_t)node * COUT))[lane] = z;
    }
}

extern "C" void kernel_launch(void* const* d_in, const int* in_sizes, int n_in,
                              void* d_out, int out_size)
{
    const float* x   = (const float*)d_in[0];
    const void*  ei  = d_in[1];                 // int32 or int64, detected on device
    const float* Wmu = (const float*)d_in[2];
    const float* bmu = (const float*)d_in[3];
    const float* Wls = (const float*)d_in[4];
    const float* bls = (const float*)d_in[5];
    const float* eps = (const float*)d_in[6];
    float*       out = (float*)d_out;

    int N = in_sizes[0] / CIN;          // 100000
    long long E = in_sizes[1] / 2;      // 1600000
    long long cap = E < 65536 ? E : 65536;

    // host-side function attribute (not a stream op; graph-capture safe)
    cudaFuncSetAttribute(gemm_kernel,
                         cudaFuncAttributeMaxDynamicSharedMemorySize, GEMM_SMEM);

    zero_kernel<<<(N + 255) / 256, 256>>>(N);
    detect_kernel<<<(int)((cap + 255) / 256), 256>>>((const long long*)ei, cap, N);
    count_kernel<<<(int)((E + 255) / 256), 256>>>(ei, E, N);
    alloc_kernel<<<(N + 255) / 256, 256>>>(N);
    fill_kernel<<<(int)((E + 255) / 256), 256>>>(ei, E, N);
    gemm_kernel<<<(N + 63) / 64, 256, GEMM_SMEM>>>(x, Wmu, Wls, N);
    gather_kernel<<<(N + 7) / 8, 256>>>(bmu, bls, eps, out, N);
}